// round 3
// baseline (speedup 1.0000x reference)
#include <cuda_runtime.h>

// ---------------------------------------------------------------------------
// FujiEngramModule: hash n-gram embedding + conv + gated projection
// B=4, S=4096, H=2048, E=32, N_HEAD=4, NUM_ORDERS=2 (k=2,3), PRIME=500009
// ---------------------------------------------------------------------------

#define BB 4
#define SS 4096
#define HH 2048
#define EE 32
#define NROWS (BB * SS)          // 16384
#define PRIME_C 500009ULL
#define VOCAB_C 128000

#define KC 32                    // K chunk for gate GEMM
#define MT 128                   // rows per CTA tile in fused kernel
#define HSS 33                   // padded row stride in smem

// Scratch (allocation-free rule: device globals)
__device__ __align__(16) float g_embpre[NROWS * EE];    // pre-conv embedding, 2 MB
__device__ __align__(16) float g_Wgt[HH * EE];          // Wg transposed [k][e]
__device__ __align__(16) float g_WoT[EE * HH];          // Wo transposed [e][c]

// ---------------------------------------------------------------------------
__global__ void prep_kernel(const float* __restrict__ Wg,
                            const float* __restrict__ Wo) {
    int i = blockIdx.x * blockDim.x + threadIdx.x;
    if (i < HH * EE) {
        int k = i / EE, e = i % EE;
        g_Wgt[i] = Wg[e * HH + k];       // Wgt[k*E + e] = Wg[e][k]
        int e2 = i / HH, c = i % HH;
        g_WoT[i] = Wo[c * EE + e2];      // WoT[e*H + c] = Wo[c][e]
    }
}

__global__ void zero_out_kernel(float* out, int n) {
    int i = blockIdx.x * blockDim.x + threadIdx.x;
    if (i < n) out[i] = 0.f;
}

// ---------------------------------------------------------------------------
// Embedding kernel: per row (b,t): 8 hash gathers -> [256] vec -> @Wh.T -> [32]
// One warp per row; lane e owns output channel e.
// Integer inputs are dtype-self-detecting (int64 vs int32 delivery).
// ---------------------------------------------------------------------------
__global__ __launch_bounds__(256)
void emb_kernel(const void* __restrict__ ids_v,
                const void* __restrict__ mapping_v,
                const void* __restrict__ mult_v,
                const float* __restrict__ table,
                const float* __restrict__ Wh) {
    // ---- dtype detection (reads stay within int32-sized footprint) ----
    const int* map32 = (const int*)mapping_v;
    const long long* map64 = (const long long*)mapping_v;
    const bool m_is64 = (map32[1] == 0);           // arange: int64 -> [0,0,1,0,..]

    const int* mlt32 = (const int*)mult_v;
    const long long* mlt64 = (const long long*)mult_v;
    const bool u_is64 = (mlt32[1] == 0);           // int64 hi-word of elem0 is 0

    const int* ids32 = (const int*)ids_v;
    const long long* ids64 = (const long long*)ids_v;   // same dtype as mapping

    __shared__ float WhT[256 * 32];      // WhT[j][e] = Wh[e][j], 32 KB
    int tid = threadIdx.x;
    for (int i = tid; i < 256 * 32; i += blockDim.x) {
        int j = i >> 5, e = i & 31;
        WhT[i] = Wh[e * 256 + j];
    }
    __syncthreads();

    int lane = tid & 31;
    int warp = tid >> 5;
    int gw = blockIdx.x * (blockDim.x >> 5) + warp;
    int nw = gridDim.x * (blockDim.x >> 5);

    // multipliers: [order][head][p]; flattened head hh = order*4+head
    unsigned long long mu0 = 0, mu1 = 0, mu2 = 0;
    if (lane < 8) {
        if (u_is64) {
            mu0 = (unsigned long long)mlt64[lane * 3 + 0];
            mu1 = (unsigned long long)mlt64[lane * 3 + 1];
            mu2 = (unsigned long long)mlt64[lane * 3 + 2];
        } else {
            mu0 = (unsigned long long)(unsigned)mlt32[lane * 3 + 0];
            mu1 = (unsigned long long)(unsigned)mlt32[lane * 3 + 1];
            mu2 = (unsigned long long)(unsigned)mlt32[lane * 3 + 2];
        }
    }

    for (int r = gw; r < NROWS; r += nw) {
        int b = r >> 12, t = r & (SS - 1);
        int t1 = min(t + 1, SS - 1);
        int t2 = min(t + 2, SS - 1);
        size_t base = (size_t)b * SS;

        int v0, v1, v2;
        if (m_is64) {
            v0 = (int)ids64[base + t];
            v1 = (int)ids64[base + t1];
            v2 = (int)ids64[base + t2];
        } else {
            v0 = ids32[base + t];
            v1 = ids32[base + t1];
            v2 = ids32[base + t2];
        }
        v0 = min(max(v0, 0), VOCAB_C - 1);   // defensive clamp
        v1 = min(max(v1, 0), VOCAB_C - 1);
        v2 = min(max(v2, 0), VOCAB_C - 1);

        unsigned long long c0, c1, c2;
        if (m_is64) {
            c0 = (unsigned long long)map64[v0];
            c1 = (unsigned long long)map64[v1];
            c2 = (unsigned long long)map64[v2];
        } else {
            c0 = (unsigned long long)(unsigned)map32[v0];
            c1 = (unsigned long long)(unsigned)map32[v1];
            c2 = (unsigned long long)(unsigned)map32[v2];
        }

        long long idx = 0;
        if (lane < 8) {
            unsigned long long h;
            if (lane < 4) h = (c0 * mu0) ^ (c1 * mu1);                 // bigram
            else          h = (c0 * mu0) ^ (c1 * mu1) ^ (c2 * mu2);    // trigram
            idx = (long long)(h % PRIME_C) + (long long)lane * (long long)PRIME_C;
            if (idx < 0) idx = 0;
            if (idx > 4000071LL) idx = 4000071LL;   // defensive clamp
        }

        float acc = 0.f;
        #pragma unroll
        for (int hh = 0; hh < 8; hh++) {
            long long ih = __shfl_sync(0xffffffffu, idx, hh);
            float tv = table[ih * 32 + lane];          // coalesced 128B row
            const float* wp = &WhT[(hh * 32) * 32 + lane];
            #pragma unroll
            for (int j = 0; j < 32; j++) {
                acc = fmaf(__shfl_sync(0xffffffffu, tv, j), wp[j * 32], acc);
            }
        }
        g_embpre[(size_t)r * EE + lane] = acc;
    }
}

// ---------------------------------------------------------------------------
// Fused kernel: gate GEMM (K=2048) + sigmoid + causal conv + out GEMM (N=2048)
// One CTA = 128 rows, 256 threads.
// ---------------------------------------------------------------------------
__global__ __launch_bounds__(256, 1)
void fused_kernel(const float* __restrict__ hidden,
                  const float* __restrict__ conv_w,
                  const float* __restrict__ conv_b,
                  float* __restrict__ out) {
    __shared__ __align__(16) float hs[2][MT * HSS];   // hidden tile [m][kk]
    __shared__ __align__(16) float ws[2][KC * EE];    // Wgt tile [kk][e]
    float* v_s = hs[0];                               // reused after phase A

    int tid = threadIdx.x;
    int r0 = blockIdx.x * MT;
    int tm = tid >> 3;    // 0..31
    int te = tid & 7;     // 0..7

    float a[4][4];
    #pragma unroll
    for (int i = 0; i < 4; i++)
        #pragma unroll
        for (int j = 0; j < 4; j++) a[i][j] = 0.f;

    {
        #pragma unroll
        for (int it = 0; it < 4; it++) {
            float4 hv = *(const float4*)(hidden + (size_t)(r0 + tm + it * 32) * HH + te * 4);
            int base = (tm + it * 32) * HSS + te * 4;
            hs[0][base + 0] = hv.x; hs[0][base + 1] = hv.y;
            hs[0][base + 2] = hv.z; hs[0][base + 3] = hv.w;
        }
        float4 wv = *(const float4*)(g_Wgt + (size_t)tm * EE + te * 4);
        int wb = tm * EE + te * 4;
        ws[0][wb + 0] = wv.x; ws[0][wb + 1] = wv.y;
        ws[0][wb + 2] = wv.z; ws[0][wb + 3] = wv.w;
    }
    __syncthreads();

    int cur = 0;
    for (int ch = 0; ch < HH / KC; ch++) {
        float4 hreg[4]; float4 wreg;
        bool pref = (ch < HH / KC - 1);
        if (pref) {
            int k0n = (ch + 1) * KC;
            #pragma unroll
            for (int it = 0; it < 4; it++)
                hreg[it] = *(const float4*)(hidden + (size_t)(r0 + tm + it * 32) * HH + k0n + te * 4);
            wreg = *(const float4*)(g_Wgt + (size_t)(k0n + tm) * EE + te * 4);
        }

        const float* hb = hs[cur];
        const float* wb = ws[cur];
        #pragma unroll
        for (int kk = 0; kk < KC; kk++) {
            float4 wv = *(const float4*)&wb[kk * EE + te * 4];
            float h0 = hb[(tm * 4 + 0) * HSS + kk];
            float h1 = hb[(tm * 4 + 1) * HSS + kk];
            float h2 = hb[(tm * 4 + 2) * HSS + kk];
            float h3 = hb[(tm * 4 + 3) * HSS + kk];
            a[0][0] = fmaf(h0, wv.x, a[0][0]); a[0][1] = fmaf(h0, wv.y, a[0][1]);
            a[0][2] = fmaf(h0, wv.z, a[0][2]); a[0][3] = fmaf(h0, wv.w, a[0][3]);
            a[1][0] = fmaf(h1, wv.x, a[1][0]); a[1][1] = fmaf(h1, wv.y, a[1][1]);
            a[1][2] = fmaf(h1, wv.z, a[1][2]); a[1][3] = fmaf(h1, wv.w, a[1][3]);
            a[2][0] = fmaf(h2, wv.x, a[2][0]); a[2][1] = fmaf(h2, wv.y, a[2][1]);
            a[2][2] = fmaf(h2, wv.z, a[2][2]); a[2][3] = fmaf(h2, wv.w, a[2][3]);
            a[3][0] = fmaf(h3, wv.x, a[3][0]); a[3][1] = fmaf(h3, wv.y, a[3][1]);
            a[3][2] = fmaf(h3, wv.z, a[3][2]); a[3][3] = fmaf(h3, wv.w, a[3][3]);
        }

        if (pref) {
            int nxt = cur ^ 1;
            #pragma unroll
            for (int it = 0; it < 4; it++) {
                int base = (tm + it * 32) * HSS + te * 4;
                hs[nxt][base + 0] = hreg[it].x; hs[nxt][base + 1] = hreg[it].y;
                hs[nxt][base + 2] = hreg[it].z; hs[nxt][base + 3] = hreg[it].w;
            }
            int wb2 = tm * EE + te * 4;
            ws[nxt][wb2 + 0] = wreg.x; ws[nxt][wb2 + 1] = wreg.y;
            ws[nxt][wb2 + 2] = wreg.z; ws[nxt][wb2 + 3] = wreg.w;
        }
        __syncthreads();
        cur ^= 1;
    }

    // ---- gate + causal conv + elementwise product -> v_s[m][e] ----
    #pragma unroll
    for (int i = 0; i < 4; i++) {
        int m = tm * 4 + i;
        int r = r0 + m;
        int t = r & (SS - 1);
        #pragma unroll
        for (int j = 0; j < 4; j++) {
            int e = te * 4 + j;
            float x = a[i][j];
            float g = 1.f / (1.f + __expf(-x));
            float ce = conv_b[e];
            #pragma unroll
            for (int jj = 0; jj < 4; jj++) {
                int tt = t + jj - 3;
                if (tt >= 0)
                    ce = fmaf(conv_w[e * 4 + jj], g_embpre[(size_t)(r + jj - 3) * EE + e], ce);
            }
            v_s[m * HSS + e] = g * ce;
        }
    }
    __syncthreads();

    // ---- Phase B: out[m][c] = sum_e v[m][e] * WoT[e][c] ----
    int tm2 = tid >> 3;   // 0..31 (4 rows each)
    int tc2 = tid & 7;    // 0..7  (8 cols per pass)
    for (int cp = 0; cp < HH / 64; cp++) {
        int cbase = cp * 64 + tc2 * 8;
        float o[4][8];
        #pragma unroll
        for (int i = 0; i < 4; i++)
            #pragma unroll
            for (int j = 0; j < 8; j++) o[i][j] = 0.f;

        #pragma unroll 8
        for (int e = 0; e < EE; e++) {
            float4 w1 = *(const float4*)(g_WoT + (size_t)e * HH + cbase);
            float4 w2 = *(const float4*)(g_WoT + (size_t)e * HH + cbase + 4);
            #pragma unroll
            for (int i = 0; i < 4; i++) {
                float vv = v_s[(tm2 * 4 + i) * HSS + e];
                o[i][0] = fmaf(vv, w1.x, o[i][0]); o[i][1] = fmaf(vv, w1.y, o[i][1]);
                o[i][2] = fmaf(vv, w1.z, o[i][2]); o[i][3] = fmaf(vv, w1.w, o[i][3]);
                o[i][4] = fmaf(vv, w2.x, o[i][4]); o[i][5] = fmaf(vv, w2.y, o[i][5]);
                o[i][6] = fmaf(vv, w2.z, o[i][6]); o[i][7] = fmaf(vv, w2.w, o[i][7]);
            }
        }
        #pragma unroll
        for (int i = 0; i < 4; i++) {
            float* op = out + (size_t)(r0 + tm2 * 4 + i) * HH + cbase;
            *(float4*)(op)     = make_float4(o[i][0], o[i][1], o[i][2], o[i][3]);
            *(float4*)(op + 4) = make_float4(o[i][4], o[i][5], o[i][6], o[i][7]);
        }
    }
}

// ---------------------------------------------------------------------------
// Size-based input dispatch (robust to metadata ordering). Wg/Wo tie (65536)
// broken by first-occurrence (Wg precedes Wo in dict AND alphabetical order).
// ---------------------------------------------------------------------------
extern "C" void kernel_launch(void* const* d_in, const int* in_sizes, int n_in,
                              void* d_out, int out_size) {
    const void* ids = 0;
    const float* hidden = 0;
    const void* mapping = 0;
    const void* mult = 0;
    const float* table = 0;
    const float* conv_w = 0;
    const float* conv_b = 0;
    const float* Wh = 0;
    const float* Wg = 0;
    const float* Wo = 0;

    for (int i = 0; i < n_in; i++) {
        long long n = in_sizes[i];
        void* p = d_in[i];
        if      (n == 16384LL)       ids     = p;
        else if (n == 33554432LL)    hidden  = (const float*)p;
        else if (n == 128000LL)      mapping = p;
        else if (n == 24LL)          mult    = p;
        else if (n == 128002304LL)   table   = (const float*)p;
        else if (n == 128LL)         conv_w  = (const float*)p;
        else if (n == 32LL)          conv_b  = (const float*)p;
        else if (n == 8192LL)        Wh      = (const float*)p;
        else if (n == 65536LL) {
            if (!Wg) Wg = (const float*)p; else Wo = (const float*)p;
        }
    }

    float* out = (float*)d_out;

    if (!ids || !hidden || !mapping || !mult || !table ||
        !conv_w || !conv_b || !Wh || !Wg || !Wo) {
        // Dispatch failed: produce a distinct failure signature (numeric
        // mismatch, not IMA) so the next round can diagnose.
        zero_out_kernel<<<(out_size + 255) / 256, 256>>>(out, out_size);
        return;
    }

    prep_kernel<<<(HH * EE + 255) / 256, 256>>>(Wg, Wo);
    emb_kernel<<<296, 256>>>(ids, mapping, mult, table, Wh);
    fused_kernel<<<NROWS / MT, 256>>>(hidden, conv_w, conv_b, out);
}